// round 10
// baseline (speedup 1.0000x reference)
#include <cuda_runtime.h>
#include <cuda_bf16.h>
#include <cstdint>
#include <math.h>

typedef unsigned long long u64;

#define L_   256
#define B_   128
#define D_   256
#define H_   256
#define NCOL 2048            // 2 dirs * 4H packed gate columns
#define HALF 16777216        // L*B*2H  (cells block size; hiddens follow)

// rec smem layout (float offsets)
#define F_W      0           // Wp2: [128 kpair][64 cpair][2 k] f32x2  = 131072 B (32768 f)
#define F_SH2    32768       // sh2: [16 b][260] u64 dup-pairs        = 33280 B  (8320 f)
#define F_G1     41088       // gates lo: [16 b][132]                 = 8448 B   (2112 f)
#define F_G2     43200       // gates hi: [16 b][132]                 = 8448 B   (2112 f)
#define F_SC     45312       // sc: [16 b][32]                        = 2048 B   (512 f)
#define F_PAR    45824       // parents: [256 s][16 b] int            = 16384 B  (4096 f)
#define DYN_SMEM 199680

// ------------------------- __device__ scratch (no runtime alloc) -------------------------
__device__ float g_wx[(size_t)NCOL * D_];
__device__ float g_bias[NCOL];
__device__ float g_xi[(size_t)L_ * B_ * NCOL];
__device__ float g_acc_c[(size_t)B_ * 257 * H_];
__device__ float g_acc_h[(size_t)B_ * 257 * H_];
__device__ float g_td_h[(size_t)L_ * B_ * H_];
__device__ float g_td_c[(size_t)L_ * B_ * H_];

// ------------------------- f32x2 packed-FMA helpers (Blackwell) -------------------------
__device__ __forceinline__ void fma2(u64& c, u64 a, u64 b) {
    asm("fma.rn.f32x2 %0, %1, %2, %3;" : "=l"(c) : "l"(a), "l"(b), "l"(c));
}
__device__ __forceinline__ u64 pk2(float x) {
    u64 r; asm("mov.b64 %0, {%1, %1};" : "=l"(r) : "f"(x)); return r;
}
__device__ __forceinline__ float2 up2(u64 v) {
    float2 f; asm("mov.b64 {%0, %1}, %2;" : "=f"(f.x), "=f"(f.y) : "l"(v)); return f;
}
__device__ __forceinline__ float sigm(float x) { return 1.0f / (1.0f + __expf(-x)); }

// ------------------------- pack x-weights + fused biases -------------------------
__global__ void pack_wx_kernel(const float* __restrict__ ioux_w, const float* __restrict__ ioux_b,
                               const float* __restrict__ iouh_b, const float* __restrict__ fx_w,
                               const float* __restrict__ fx_b, const float* __restrict__ fh_b,
                               int base) {
    int c = blockIdx.x;    // 0..1023
    int k = threadIdx.x;   // 0..255
    const float* src = (c < 768) ? (ioux_w + (size_t)c * D_) : (fx_w + (size_t)(c - 768) * D_);
    g_wx[(size_t)(base + c) * D_ + k] = src[k];
    if (k == 0)
        g_bias[base + c] = (c < 768) ? (ioux_b[c] + iouh_b[c]) : (fx_b[c - 768] + fh_b[c - 768]);
}

// ------------------------- precompute GEMM (f32x2): g_xi = inputs @ g_wx^T + g_bias ----------
__global__ __launch_bounds__(256) void xgemm_kernel(const float* __restrict__ A) {
    __shared__ u64 As2[16][65];
    __shared__ float Bs[16][68];
    int mBase = blockIdx.x * 64;
    int nBase = blockIdx.y * 64;
    int t = threadIdx.x;
    int tx = t & 15, ty = t >> 4;
    int lm = t >> 2;
    int lk = (t & 3) * 4;
    u64 acc[4][2] = {};
    for (int kt = 0; kt < 256; kt += 16) {
        float4 av = *(const float4*)(A + (size_t)(mBase + lm) * D_ + kt + lk);
        float4 bv = *(const float4*)(g_wx + (size_t)(nBase + lm) * D_ + kt + lk);
        As2[lk + 0][lm] = pk2(av.x); As2[lk + 1][lm] = pk2(av.y);
        As2[lk + 2][lm] = pk2(av.z); As2[lk + 3][lm] = pk2(av.w);
        Bs[lk + 0][lm] = bv.x; Bs[lk + 1][lm] = bv.y; Bs[lk + 2][lm] = bv.z; Bs[lk + 3][lm] = bv.w;
        __syncthreads();
#pragma unroll
        for (int k = 0; k < 16; k++) {
            u64 a0 = As2[k][ty * 4 + 0];
            u64 a1 = As2[k][ty * 4 + 1];
            u64 a2 = As2[k][ty * 4 + 2];
            u64 a3 = As2[k][ty * 4 + 3];
            ulonglong2 wv = *(const ulonglong2*)(&Bs[k][tx * 4]);
            fma2(acc[0][0], a0, wv.x); fma2(acc[0][1], a0, wv.y);
            fma2(acc[1][0], a1, wv.x); fma2(acc[1][1], a1, wv.y);
            fma2(acc[2][0], a2, wv.x); fma2(acc[2][1], a2, wv.y);
            fma2(acc[3][0], a3, wv.x); fma2(acc[3][1], a3, wv.y);
        }
        __syncthreads();
    }
    float4 bias = *(const float4*)(g_bias + nBase + tx * 4);
#pragma unroll
    for (int i = 0; i < 4; i++) {
        float2 lo = up2(acc[i][0]);
        float2 hi = up2(acc[i][1]);
        float4 o;
        o.x = lo.x + bias.x;
        o.y = lo.y + bias.y;
        o.z = hi.x + bias.z;
        o.w = hi.y + bias.w;
        *(float4*)(g_xi + (size_t)(mBase + ty * 4 + i) * NCOL + nBase + tx * 4) = o;
    }
}

// ------------------------- recurrent scan kernel (weights read ONCE per step) ----------------
// 128 CTAs = 16 clusters of 8. cluster id -> (dir, batch group of 16).
// CTA rank r owns gate columns cc = g*32+j; its 128KB Wh slice is smem-resident in a
// k-pair/col-pair f32x2 layout. 16 warps = kset(2 k-halves) x 8 col-groups of 16 cols;
// thread = 1 col-pair x 4 batches -> weights are loaded exactly once per step.
// Cross-CTA h/c exchange: L2 (__ldcg/__stcg/REDG) + barrier.cluster release/acquire.
__global__ __launch_bounds__(512, 1) __cluster_dims__(8, 1, 1)
void rec_kernel(const int* __restrict__ parents,
                const float* __restrict__ dt_iouh_w, const float* __restrict__ dt_fh_w,
                const float* __restrict__ td_iouh_w, const float* __restrict__ td_fh_w,
                float* __restrict__ out) {
    extern __shared__ float smem[];
    float* Wf      = smem + F_W;
    u64*   Wp2     = (u64*)(smem + F_W);       // elem ((k>>1)*64+cpg)*2+(k&1) = cols(2cpg,2cpg+1)@k
    u64*   sh2     = (u64*)(smem + F_SH2);     // [16 b][260] dup-pairs (row padded: +4)
    float* gates_s = smem + F_G1;              // [16 b][132] partial k-lo
    float* gates2_s= smem + F_G2;              // [16 b][132] partial k-hi
    float* sc_s    = smem + F_SC;              // [16 b][32]
    int*   par_all = (int*)(smem + F_PAR);     // [256 s][16 b]

    const int blk = blockIdx.x;
    const int r   = blk & 7;           // cluster rank -> h-dim slice [r*32, r*32+32)
    const int cid = blk >> 3;
    const int dir = cid >> 3;          // 0 = dt (bottom-up), 1 = td (top-down)
    const int bg  = cid & 7;           // batch group (16 batches)
    const int t   = threadIdx.x;
    const int lane = t & 31;
    const int wid  = t >> 5;

    const float* iouh = dir ? td_iouh_w : dt_iouh_w;
    const float* fh   = dir ? td_fh_w : dt_fh_w;

    // ---- one-time: Wh slice -> k-pair/col-pair smem layout ----
    {
        int cc = t & 127;              // gate column: g*32+j
        int g = cc >> 5, j = cc & 31;
        const float* src = (g < 3) ? (iouh + (size_t)(g * 256 + r * 32 + j) * H_)
                                   : (fh + (size_t)(r * 32 + j) * H_);
        int k0 = (t >> 7) * 64;
        for (int k = k0; k < k0 + 64; k++) {
            int idx = ((((k >> 1) * 64) + (cc >> 1)) * 2 + (k & 1)) * 2 + (cc & 1);
            Wf[idx] = src[k];
        }
    }
    // ---- one-time: parents (node per step is static: dt 255-s, td s) ----
    if (t < 256) {
        int s = t;
        int node = dir ? s : (255 - s);
#pragma unroll 4
        for (int j = 0; j < 16; j++)
            par_all[s * 16 + j] = parents[node * B_ + bg * 16 + j];
    }

    // GEMM mapping: kset = wid>>3 (k half), w8 = wid&7 (16 cols), cp = lane&7, bq = lane>>3
    const int kset = wid >> 3;
    const int w8   = wid & 7;
    const int cp   = lane & 7;
    const int bq   = lane >> 3;
    const int cpg  = w8 * 8 + cp;          // global col pair -> cols (2cpg, 2cpg+1)
    float* gbuf = kset ? gates2_s : gates_s;

    // epilogue mapping: 1 gate-dim per thread
    const int ebb = t >> 5;
    const int ejj = t & 31;
    const int eb  = bg * 16 + ebb;
    // c-gather mapping (t < 256, slice-private, overlapped behind arrive)
    const int cbb = t >> 4;
    const int cdd = (t & 15) * 2;
    const int cb  = bg * 16 + cbb;

    // ---- prologue: sc + xi prefetch for step 0 ----
    if (t < 256) {
        int node0 = dir ? 0 : 255;
        float2 v;
        if (dir) v = make_float2(0.f, 0.f);    // node 0's parent is the root dummy
        else v = __ldcg((const float2*)(g_acc_c + ((size_t)cb * 257 + node0) * 256 + r * 32 + cdd));
        sc_s[cbb * 32 + cdd] = v.x;
        sc_s[cbb * 32 + cdd + 1] = v.y;
    }
    float xi0, xi1, xi2, xi3;
    {
        int node0 = dir ? 0 : 255;
        const float* xb = g_xi + ((size_t)node0 * B_ + eb) * NCOL + dir * 1024 + r * 32 + ejj;
        xi0 = __ldcg(xb); xi1 = __ldcg(xb + 256); xi2 = __ldcg(xb + 512); xi3 = __ldcg(xb + 768);
    }
    __syncthreads();
    asm volatile("barrier.cluster.arrive.aligned;" ::: "memory");

    for (int s = 0; s < 256; s++) {
        const int node = dir ? s : (255 - s);
        const int sb = s * 16;

        // ---- wait for peers' step s-1 writes (acquire) ----
        asm volatile("barrier.cluster.wait.aligned;" ::: "memory");

        // ---- gather h rows (dt: child sums at node; td: parent h), dup-packed ----
        {
            int fbb = t >> 5;              // 16 rows, one per warp
            int b = bg * 16 + fbb;
            const float* src;
            bool zero = false;
            if (dir) {
                int p = par_all[sb + fbb];
                zero = (p == 256);
                src = g_td_h + ((size_t)p * B_ + b) * 256;
            } else {
                src = g_acc_h + ((size_t)b * 257 + node) * 256;
            }
#pragma unroll
            for (int q = 0; q < 2; q++) {
                int pos = (lane + q * 32) * 4;
                float4 v = zero ? make_float4(0.f, 0.f, 0.f, 0.f)
                                : __ldcg((const float4*)(src + pos));
                *(ulonglong2*)(sh2 + fbb * 260 + pos)     = make_ulonglong2(pk2(v.x), pk2(v.y));
                *(ulonglong2*)(sh2 + fbb * 260 + pos + 2) = make_ulonglong2(pk2(v.z), pk2(v.w));
            }
        }
        __syncthreads();   // #1: sh2 ready

        // ---- GEMM partial: gbuf[b][2cpg..2cpg+1] = sum_{k in half} h[b][k] * W[col][k] ----
        {
            u64 a0 = 0, a1 = 0, a2 = 0, a3 = 0;
            const u64* hb = sh2 + bq * 260 + kset * 128;
            const u64* wb = Wp2 + ((size_t)(kset * 64) * 64 + cpg) * 2;
#pragma unroll 8
            for (int kp = 0; kp < 64; kp++) {
                ulonglong2 wv = *(const ulonglong2*)(wb + kp * 128);
                ulonglong2 h0 = *(const ulonglong2*)(hb + kp * 2);
                ulonglong2 h1 = *(const ulonglong2*)(hb + 4 * 260 + kp * 2);
                ulonglong2 h2 = *(const ulonglong2*)(hb + 8 * 260 + kp * 2);
                ulonglong2 h3 = *(const ulonglong2*)(hb + 12 * 260 + kp * 2);
                fma2(a0, h0.x, wv.x); fma2(a0, h0.y, wv.y);
                fma2(a1, h1.x, wv.x); fma2(a1, h1.y, wv.y);
                fma2(a2, h2.x, wv.x); fma2(a2, h2.y, wv.y);
                fma2(a3, h3.x, wv.x); fma2(a3, h3.y, wv.y);
            }
            int gcol = w8 * 16 + cp * 2;
            *(u64*)(gbuf + (bq + 0)  * 132 + gcol) = a0;
            *(u64*)(gbuf + (bq + 4)  * 132 + gcol) = a1;
            *(u64*)(gbuf + (bq + 8)  * 132 + gcol) = a2;
            *(u64*)(gbuf + (bq + 12) * 132 + gcol) = a3;
        }
        __syncthreads();   // #2: gates ready

        // ---- epilogue: combine k-halves + xi, nonlinearities, state update, scatter ----
        {
            int p = par_all[sb + ebb];
            float iv = gates_s[ebb * 132 + ejj]      + gates2_s[ebb * 132 + ejj]      + xi0;
            float ov = gates_s[ebb * 132 + 32 + ejj] + gates2_s[ebb * 132 + 32 + ejj] + xi1;
            float uv = gates_s[ebb * 132 + 64 + ejj] + gates2_s[ebb * 132 + 64 + ejj] + xi2;
            float fv = gates_s[ebb * 132 + 96 + ejj] + gates2_s[ebb * 132 + 96 + ejj] + xi3;
            float sc = sc_s[ebb * 32 + ejj];
            float ig = sigm(iv);
            float og = sigm(ov);
            float ug = tanhf(uv);
            float fg = sigm(fv);
            float c = ig * ug + fg * sc;
            float h = og * tanhf(c);
            size_t orow = ((size_t)node * B_ + eb) * 512 + (size_t)dir * 256 + r * 32 + ejj;
            __stcg(out + orow, c);
            __stcg(out + HALF + orow, h);
            if (dir) {
                size_t trow = ((size_t)node * B_ + eb) * 256 + r * 32 + ejj;
                __stcg(g_td_h + trow, h);
                __stcg(g_td_c + trow, c);
            } else {
                size_t arow = ((size_t)eb * 257 + p) * 256 + r * 32 + ejj;
                atomicAdd(&g_acc_h[arow], h);   // result unused -> REDG
                atomicAdd(&g_acc_c[arow], c);
            }
        }
        __syncthreads();   // #3: epilogue done (gates/sc consumed)

        if (s < 255) {
            // ---- publish step s (release); overlap slice-private prefetches ----
            asm volatile("barrier.cluster.arrive.aligned;" ::: "memory");

            int node2 = dir ? (s + 1) : (254 - s);
            if (t < 256) {
                float2 v;
                if (dir) {
                    int p2 = par_all[sb + 16 + cbb];
                    if (p2 == 256) v = make_float2(0.f, 0.f);
                    else v = __ldcg((const float2*)(g_td_c + ((size_t)p2 * B_ + cb) * 256 + r * 32 + cdd));
                } else {
                    v = __ldcg((const float2*)(g_acc_c + ((size_t)cb * 257 + node2) * 256 + r * 32 + cdd));
                }
                sc_s[cbb * 32 + cdd] = v.x;
                sc_s[cbb * 32 + cdd + 1] = v.y;
            }
            const float* xb = g_xi + ((size_t)node2 * B_ + eb) * NCOL + dir * 1024 + r * 32 + ejj;
            xi0 = __ldcg(xb); xi1 = __ldcg(xb + 256); xi2 = __ldcg(xb + 512); xi3 = __ldcg(xb + 768);
        }
    }
}

// ------------------------- launch -------------------------
extern "C" void kernel_launch(void* const* d_in, const int* in_sizes, int n_in,
                              void* d_out, int out_size) {
    const float* inputs = (const float*)d_in[0];
    const int* parents = (const int*)d_in[2];

    // pack x-side weights + fused biases (dt -> cols [0,1024), td -> [1024,2048))
    pack_wx_kernel<<<1024, 256>>>((const float*)d_in[3], (const float*)d_in[4],
                                  (const float*)d_in[6], (const float*)d_in[7],
                                  (const float*)d_in[8], (const float*)d_in[10], 0);
    pack_wx_kernel<<<1024, 256>>>((const float*)d_in[11], (const float*)d_in[12],
                                  (const float*)d_in[14], (const float*)d_in[15],
                                  (const float*)d_in[16], (const float*)d_in[18], 1024);

    // precompute x projections for all nodes/batches/dirs
    dim3 gg(512, 32);
    xgemm_kernel<<<gg, 256>>>(inputs);

    // zero dt accumulators (scan state) every launch
    void* accc = nullptr; void* acch = nullptr;
    cudaGetSymbolAddress(&accc, g_acc_c);
    cudaGetSymbolAddress(&acch, g_acc_h);
    cudaMemsetAsync(accc, 0, sizeof(float) * (size_t)B_ * 257 * H_);
    cudaMemsetAsync(acch, 0, sizeof(float) * (size_t)B_ * 257 * H_);

    // recurrent scans: 16 clusters x 8 CTAs, 512 threads, 199680 B dynamic smem
    cudaFuncSetAttribute(rec_kernel, cudaFuncAttributeMaxDynamicSharedMemorySize, DYN_SMEM);
    rec_kernel<<<128, 512, DYN_SMEM>>>(parents,
                                       (const float*)d_in[5], (const float*)d_in[9],
                                       (const float*)d_in[13], (const float*)d_in[17],
                                       (float*)d_out);
}

// round 11
// speedup vs baseline: 1.0131x; 1.0131x over previous
#include <cuda_runtime.h>
#include <cuda_bf16.h>
#include <cstdint>
#include <math.h>

typedef unsigned long long u64;

#define L_   256
#define B_   128
#define D_   256
#define H_   256
#define NCOL 2048            // 2 dirs * 4H packed gate columns
#define HALF 16777216        // L*B*2H  (cells block size; hiddens follow)

// rec smem layout (float offsets)
#define F_W      0           // Wp2: [128 kpair][64 cpair][2 k]        = 131072 B
#define F_SH2    32768       // sh2: [16 row][260] u64 dup-pairs       = 33280 B
#define F_G1     41088       // gates lo: [16][132]                    = 8448 B
#define F_G2     43200       // gates hi: [16][132]                    = 8448 B
#define F_SC     45312       // sc: [16][32]                           = 2048 B
#define F_XI     45824       // xi: [16][132]                          = 8448 B
#define F_PAR    47936       // parents: [16 bl][256 n] int            = 16384 B
#define F_LIST   52032       // worklist: 4096 int                     = 16384 B
#define F_OFF    56128       // round offsets: 258 int                 = 1032 B
#define DYN_SMEM 225664

// ------------------------- __device__ scratch (no runtime alloc) -------------------------
__device__ float g_wx[(size_t)NCOL * D_];
__device__ float g_bias[NCOL];
__device__ float g_xi[(size_t)L_ * B_ * NCOL];
__device__ float g_acc_c[(size_t)B_ * 257 * H_];
__device__ float g_acc_h[(size_t)B_ * 257 * H_];
__device__ float g_td_h[(size_t)L_ * B_ * H_];
__device__ float g_td_c[(size_t)L_ * B_ * H_];
__device__ int   g_rankbuf[2 * 128 * 256];   // [dir][b][node] dependency rank
__device__ int   g_wl[16 * 4096];            // per-cluster worklist (bl<<8|node), rank-sorted
__device__ int   g_offs[16 * 258];           // per-cluster round offsets
__device__ int   g_nrounds[16];

// ------------------------- f32x2 packed-FMA helpers (Blackwell) -------------------------
__device__ __forceinline__ void fma2(u64& c, u64 a, u64 b) {
    asm("fma.rn.f32x2 %0, %1, %2, %3;" : "=l"(c) : "l"(a), "l"(b), "l"(c));
}
__device__ __forceinline__ u64 pk2(float x) {
    u64 r; asm("mov.b64 %0, {%1, %1};" : "=l"(r) : "f"(x)); return r;
}
__device__ __forceinline__ float2 up2(u64 v) {
    float2 f; asm("mov.b64 {%0, %1}, %2;" : "=f"(f.x), "=f"(f.y) : "l"(v)); return f;
}
__device__ __forceinline__ float sigm(float x) { return 1.0f / (1.0f + __expf(-x)); }

// ------------------------- rank kernel: dependency depth per (dir, batch, node) -------------
__global__ void rank_kernel(const int* __restrict__ parents) {
    int tid = threadIdx.x;              // 0..255
    int dir = tid >> 7, b = tid & 127;
    int rr[256];
    if (dir) {                          // td: rank = depth from root
        rr[0] = 0;
        for (int i = 1; i < 256; i++) rr[i] = rr[parents[i * B_ + b]] + 1;
    } else {                            // dt: rank = height above leaves
        for (int i = 0; i < 256; i++) rr[i] = 0;
        for (int i = 255; i >= 1; i--) {
            int p = parents[i * B_ + b];
            int v = rr[i] + 1;
            if (rr[p] < v) rr[p] = v;
        }
    }
    for (int i = 0; i < 256; i++) g_rankbuf[(dir * 128 + b) * 256 + i] = rr[i];
}

// ------------------------- worklist kernel: counting sort by rank per cluster ---------------
__global__ void wlist_kernel() {
    __shared__ int cnt[258], pos[258];
    __shared__ int maxr;
    int cl = blockIdx.x;                // 16 clusters = dir*8 + bg
    int dir = cl >> 3, bg = cl & 7;
    int t = threadIdx.x;
    for (int i = t; i < 258; i += 256) cnt[i] = 0;
    if (t == 0) maxr = 0;
    __syncthreads();
    for (int idx = t; idx < 4096; idx += 256) {
        int bl = idx >> 8, n = idx & 255;
        int rk = g_rankbuf[(dir * 128 + bg * 16 + bl) * 256 + n];
        atomicAdd(&cnt[rk], 1);
        atomicMax(&maxr, rk);
    }
    __syncthreads();
    if (t == 0) {
        int acc = 0;
        for (int i = 0; i <= maxr + 1; i++) {
            pos[i] = acc;
            g_offs[cl * 258 + i] = acc;
            acc += cnt[i];
        }
        g_nrounds[cl] = maxr + 1;
    }
    __syncthreads();
    for (int idx = t; idx < 4096; idx += 256) {
        int bl = idx >> 8, n = idx & 255;
        int rk = g_rankbuf[(dir * 128 + bg * 16 + bl) * 256 + n];
        int p = atomicAdd(&pos[rk], 1);
        g_wl[cl * 4096 + p] = (bl << 8) | n;
    }
}

// ------------------------- pack x-weights + fused biases -------------------------
__global__ void pack_wx_kernel(const float* __restrict__ ioux_w, const float* __restrict__ ioux_b,
                               const float* __restrict__ iouh_b, const float* __restrict__ fx_w,
                               const float* __restrict__ fx_b, const float* __restrict__ fh_b,
                               int base) {
    int c = blockIdx.x;
    int k = threadIdx.x;
    const float* src = (c < 768) ? (ioux_w + (size_t)c * D_) : (fx_w + (size_t)(c - 768) * D_);
    g_wx[(size_t)(base + c) * D_ + k] = src[k];
    if (k == 0)
        g_bias[base + c] = (c < 768) ? (ioux_b[c] + iouh_b[c]) : (fx_b[c - 768] + fh_b[c - 768]);
}

// ------------------------- precompute GEMM (f32x2): g_xi = inputs @ g_wx^T + g_bias ----------
__global__ __launch_bounds__(256) void xgemm_kernel(const float* __restrict__ A) {
    __shared__ u64 As2[16][65];
    __shared__ float Bs[16][68];
    int mBase = blockIdx.x * 64;
    int nBase = blockIdx.y * 64;
    int t = threadIdx.x;
    int tx = t & 15, ty = t >> 4;
    int lm = t >> 2;
    int lk = (t & 3) * 4;
    u64 acc[4][2] = {};
    for (int kt = 0; kt < 256; kt += 16) {
        float4 av = *(const float4*)(A + (size_t)(mBase + lm) * D_ + kt + lk);
        float4 bv = *(const float4*)(g_wx + (size_t)(nBase + lm) * D_ + kt + lk);
        As2[lk + 0][lm] = pk2(av.x); As2[lk + 1][lm] = pk2(av.y);
        As2[lk + 2][lm] = pk2(av.z); As2[lk + 3][lm] = pk2(av.w);
        Bs[lk + 0][lm] = bv.x; Bs[lk + 1][lm] = bv.y; Bs[lk + 2][lm] = bv.z; Bs[lk + 3][lm] = bv.w;
        __syncthreads();
#pragma unroll
        for (int k = 0; k < 16; k++) {
            u64 a0 = As2[k][ty * 4 + 0];
            u64 a1 = As2[k][ty * 4 + 1];
            u64 a2 = As2[k][ty * 4 + 2];
            u64 a3 = As2[k][ty * 4 + 3];
            ulonglong2 wv = *(const ulonglong2*)(&Bs[k][tx * 4]);
            fma2(acc[0][0], a0, wv.x); fma2(acc[0][1], a0, wv.y);
            fma2(acc[1][0], a1, wv.x); fma2(acc[1][1], a1, wv.y);
            fma2(acc[2][0], a2, wv.x); fma2(acc[2][1], a2, wv.y);
            fma2(acc[3][0], a3, wv.x); fma2(acc[3][1], a3, wv.y);
        }
        __syncthreads();
    }
    float4 bias = *(const float4*)(g_bias + nBase + tx * 4);
#pragma unroll
    for (int i = 0; i < 4; i++) {
        float2 lo = up2(acc[i][0]);
        float2 hi = up2(acc[i][1]);
        float4 o;
        o.x = lo.x + bias.x;
        o.y = lo.y + bias.y;
        o.z = hi.x + bias.z;
        o.w = hi.y + bias.w;
        *(float4*)(g_xi + (size_t)(mBase + ty * 4 + i) * NCOL + nBase + tx * 4) = o;
    }
}

// ------------------------- recurrent kernel: depth-parallel rounds --------------------------
// 128 CTAs = 16 clusters of 8. cluster = (dir, batch group of 16); rank r owns 32 h-dims
// (128 gate cols), Wh slice smem-resident. Per ROUND (~height of tree, ~25): process all
// same-rank (b, node) pairs in chunks of 16 (independent — only __syncthreads between
// chunks), then ONE cluster barrier publishes the round's h/c to peer ranks via L2.
__global__ __launch_bounds__(512, 1) __cluster_dims__(8, 1, 1)
void rec_kernel(const int* __restrict__ parents,
                const float* __restrict__ dt_iouh_w, const float* __restrict__ dt_fh_w,
                const float* __restrict__ td_iouh_w, const float* __restrict__ td_fh_w,
                float* __restrict__ out) {
    extern __shared__ float smem[];
    float* Wf       = smem + F_W;
    u64*   Wp2      = (u64*)(smem + F_W);
    u64*   sh2      = (u64*)(smem + F_SH2);
    float* gates_s  = smem + F_G1;
    float* gates2_s = smem + F_G2;
    float* sc_s     = smem + F_SC;
    float* xi_s     = smem + F_XI;
    int*   par_s    = (int*)(smem + F_PAR);
    int*   list_s   = (int*)(smem + F_LIST);
    int*   off_s    = (int*)(smem + F_OFF);

    const int blk = blockIdx.x;
    const int r   = blk & 7;
    const int cid = blk >> 3;
    const int dir = cid >> 3;
    const int bg  = cid & 7;
    const int t   = threadIdx.x;
    const int lane = t & 31;
    const int wid  = t >> 5;

    const float* iouh = dir ? td_iouh_w : dt_iouh_w;
    const float* fh   = dir ? td_fh_w : dt_fh_w;

    // ---- one-time: Wh slice -> k-pair/col-pair smem layout ----
    {
        int cc = t & 127;
        int g = cc >> 5, j = cc & 31;
        const float* src = (g < 3) ? (iouh + (size_t)(g * 256 + r * 32 + j) * H_)
                                   : (fh + (size_t)(r * 32 + j) * H_);
        int k0 = (t >> 7) * 64;
        for (int k = k0; k < k0 + 64; k++) {
            int idx = ((((k >> 1) * 64) + (cc >> 1)) * 2 + (k & 1)) * 2 + (cc & 1);
            Wf[idx] = src[k];
        }
    }
    // ---- one-time: parents table, worklist, offsets ----
    for (int i = t; i < 4096; i += 512) {
        int bl = i >> 8, n = i & 255;
        par_s[i] = parents[n * B_ + bg * 16 + bl];
        list_s[i] = g_wl[cid * 4096 + i];
    }
    for (int i = t; i < 258; i += 512) off_s[i] = g_offs[cid * 258 + i];
    const int nR = g_nrounds[cid];
    __syncthreads();

    // GEMM mapping: kset = wid>>3, w8 = wid&7 (16 cols), cp = lane&7 (col pair), bq = lane>>3
    const int kset = wid >> 3;
    const int w8   = wid & 7;
    const int cp   = lane & 7;
    const int bq   = lane >> 3;
    const int cpg  = w8 * 8 + cp;
    float* gbuf = kset ? gates2_s : gates_s;
    // epilogue mapping: 1 gate-dim per thread
    const int ebb = t >> 5;
    const int ejj = t & 31;

    for (int rd = 0; rd < nR; rd++) {
        const int base = off_s[rd];
        const int end  = off_s[rd + 1];
        const int C = (end - base + 15) >> 4;

        for (int c = 0; c < C; c++) {
            // ---- gather phase: warp wid handles row wid of this chunk ----
            {
                int ridx = base + c * 16 + wid;
                int pair = (ridx < end) ? list_s[ridx] : -1;
                float4 h0 = make_float4(0.f, 0.f, 0.f, 0.f), h1 = h0, xiv = h0, scv = h0;
                if (pair >= 0) {
                    int bl = pair >> 8, n = pair & 255;
                    int b = bg * 16 + bl;
                    int p = par_s[bl * 256 + n];
                    bool zero = false;
                    const float* hsrc;
                    if (dir) {
                        zero = (p == 256);
                        hsrc = g_td_h + ((size_t)p * B_ + b) * 256;
                    } else {
                        hsrc = g_acc_h + ((size_t)b * 257 + n) * 256;
                    }
                    if (!zero) {
                        h0 = __ldcg((const float4*)(hsrc + lane * 4));
                        h1 = __ldcg((const float4*)(hsrc + 128 + lane * 4));
                    }
                    xiv = __ldcg((const float4*)(g_xi + ((size_t)n * B_ + b) * NCOL
                              + dir * 1024 + (lane >> 3) * 256 + r * 32 + (lane & 7) * 4));
                    if (lane < 8) {
                        if (dir) {
                            if (!zero)
                                scv = __ldcg((const float4*)(g_td_c + ((size_t)p * B_ + b) * 256 + r * 32 + lane * 4));
                        } else {
                            scv = __ldcg((const float4*)(g_acc_c + ((size_t)b * 257 + n) * 256 + r * 32 + lane * 4));
                        }
                    }
                }
                *(ulonglong2*)(sh2 + wid * 260 + lane * 4)           = make_ulonglong2(pk2(h0.x), pk2(h0.y));
                *(ulonglong2*)(sh2 + wid * 260 + lane * 4 + 2)       = make_ulonglong2(pk2(h0.z), pk2(h0.w));
                *(ulonglong2*)(sh2 + wid * 260 + 128 + lane * 4)     = make_ulonglong2(pk2(h1.x), pk2(h1.y));
                *(ulonglong2*)(sh2 + wid * 260 + 128 + lane * 4 + 2) = make_ulonglong2(pk2(h1.z), pk2(h1.w));
                *(float4*)(xi_s + wid * 132 + (lane >> 3) * 32 + (lane & 7) * 4) = xiv;
                if (lane < 8) *(float4*)(sc_s + wid * 32 + lane * 4) = scv;
            }
            __syncthreads();   // #1: inputs staged

            // ---- GEMM partial: gbuf[b][cols] = sum_{k in half} h[b][k] * W[col][k] ----
            {
                u64 a0 = 0, a1 = 0, a2 = 0, a3 = 0;
                const u64* hb = sh2 + bq * 260 + kset * 128;
                const u64* wb = Wp2 + ((size_t)(kset * 64) * 64 + cpg) * 2;
#pragma unroll 8
                for (int kp = 0; kp < 64; kp++) {
                    ulonglong2 wv = *(const ulonglong2*)(wb + kp * 128);
                    ulonglong2 hh0 = *(const ulonglong2*)(hb + kp * 2);
                    ulonglong2 hh1 = *(const ulonglong2*)(hb + 4 * 260 + kp * 2);
                    ulonglong2 hh2 = *(const ulonglong2*)(hb + 8 * 260 + kp * 2);
                    ulonglong2 hh3 = *(const ulonglong2*)(hb + 12 * 260 + kp * 2);
                    fma2(a0, hh0.x, wv.x); fma2(a0, hh0.y, wv.y);
                    fma2(a1, hh1.x, wv.x); fma2(a1, hh1.y, wv.y);
                    fma2(a2, hh2.x, wv.x); fma2(a2, hh2.y, wv.y);
                    fma2(a3, hh3.x, wv.x); fma2(a3, hh3.y, wv.y);
                }
                int gcol = w8 * 16 + cp * 2;
                *(u64*)(gbuf + (bq + 0)  * 132 + gcol) = a0;
                *(u64*)(gbuf + (bq + 4)  * 132 + gcol) = a1;
                *(u64*)(gbuf + (bq + 8)  * 132 + gcol) = a2;
                *(u64*)(gbuf + (bq + 12) * 132 + gcol) = a3;
            }
            __syncthreads();   // #2: gates ready

            // ---- epilogue: combine + xi, nonlinearities, state update, scatter ----
            {
                int ridx = base + c * 16 + ebb;
                int pair = (ridx < end) ? list_s[ridx] : -1;
                if (pair >= 0) {
                    int bl = pair >> 8, n = pair & 255;
                    int b = bg * 16 + bl;
                    int p = par_s[bl * 256 + n];
                    float iv = gates_s[ebb * 132 + ejj]      + gates2_s[ebb * 132 + ejj]      + xi_s[ebb * 132 + ejj];
                    float ov = gates_s[ebb * 132 + 32 + ejj] + gates2_s[ebb * 132 + 32 + ejj] + xi_s[ebb * 132 + 32 + ejj];
                    float uv = gates_s[ebb * 132 + 64 + ejj] + gates2_s[ebb * 132 + 64 + ejj] + xi_s[ebb * 132 + 64 + ejj];
                    float fv = gates_s[ebb * 132 + 96 + ejj] + gates2_s[ebb * 132 + 96 + ejj] + xi_s[ebb * 132 + 96 + ejj];
                    float sc = sc_s[ebb * 32 + ejj];
                    float ig = sigm(iv);
                    float og = sigm(ov);
                    float ug = tanhf(uv);
                    float fg = sigm(fv);
                    float cc = ig * ug + fg * sc;
                    float hh = og * tanhf(cc);
                    size_t orow = ((size_t)n * B_ + b) * 512 + (size_t)dir * 256 + r * 32 + ejj;
                    __stcg(out + orow, cc);
                    __stcg(out + HALF + orow, hh);
                    if (dir) {
                        size_t trow = ((size_t)n * B_ + b) * 256 + r * 32 + ejj;
                        __stcg(g_td_h + trow, hh);
                        __stcg(g_td_c + trow, cc);
                    } else {
                        size_t arow = ((size_t)b * 257 + p) * 256 + r * 32 + ejj;   // p==256 -> dummy
                        atomicAdd(&g_acc_h[arow], hh);
                        atomicAdd(&g_acc_c[arow], cc);
                    }
                }
            }
            __syncthreads();   // #3: chunk complete (smem reusable)
        }

        // ---- publish this round's writes to peer ranks (release/acquire) ----
        asm volatile("barrier.cluster.arrive.aligned;" ::: "memory");
        asm volatile("barrier.cluster.wait.aligned;" ::: "memory");
    }
}

// ------------------------- launch -------------------------
extern "C" void kernel_launch(void* const* d_in, const int* in_sizes, int n_in,
                              void* d_out, int out_size) {
    const float* inputs = (const float*)d_in[0];
    const int* parents = (const int*)d_in[2];

    // dependency ranks + per-cluster rank-sorted worklists
    rank_kernel<<<1, 256>>>(parents);
    wlist_kernel<<<16, 256>>>();

    // pack x-side weights + fused biases (dt -> cols [0,1024), td -> [1024,2048))
    pack_wx_kernel<<<1024, 256>>>((const float*)d_in[3], (const float*)d_in[4],
                                  (const float*)d_in[6], (const float*)d_in[7],
                                  (const float*)d_in[8], (const float*)d_in[10], 0);
    pack_wx_kernel<<<1024, 256>>>((const float*)d_in[11], (const float*)d_in[12],
                                  (const float*)d_in[14], (const float*)d_in[15],
                                  (const float*)d_in[16], (const float*)d_in[18], 1024);

    // precompute x projections for all nodes/batches/dirs
    dim3 gg(512, 32);
    xgemm_kernel<<<gg, 256>>>(inputs);

    // zero dt accumulators (scan state) every launch
    void* accc = nullptr; void* acch = nullptr;
    cudaGetSymbolAddress(&accc, g_acc_c);
    cudaGetSymbolAddress(&acch, g_acc_h);
    cudaMemsetAsync(accc, 0, sizeof(float) * (size_t)B_ * 257 * H_);
    cudaMemsetAsync(acch, 0, sizeof(float) * (size_t)B_ * 257 * H_);

    // recurrent rounds: 16 clusters x 8 CTAs, 512 threads
    cudaFuncSetAttribute(rec_kernel, cudaFuncAttributeMaxDynamicSharedMemorySize, DYN_SMEM);
    rec_kernel<<<128, 512, DYN_SMEM>>>(parents,
                                       (const float*)d_in[5], (const float*)d_in[9],
                                       (const float*)d_in[13], (const float*)d_in[17],
                                       (float*)d_out);
}